// round 3
// baseline (speedup 1.0000x reference)
#include <cuda_runtime.h>

#define Bb  2
#define Pp  128
#define Cc  8
#define Hh  16
#define KVHh 4
#define Gg  4
#define Dd  64
#define Ee  1024
#define EKVv 256
#define Tt  1024

// ---------------- scratch (device globals; no allocation allowed) -----------
__device__ float g_q[Bb*Tt*Ee];          // [B,T,E]  q = hs @ Wq
__device__ float g_kv[Bb*Tt*2*EKVv];     // [B,T,512] gk | v
__device__ float g_tk[Pp*EKVv];          // pos_emb @ Wpos
__device__ float g_ck[Cc*EKVv];          // chan_emb @ Wchan
__device__ float g_time[Bb*Hh*Tt*Pp];    // time_att (pre-shift)
__device__ float g_chan[Bb*Hh*Tt*Cc];    // chan_att (pre-shift)
__device__ float g_ao[Bb*Tt*Ee];         // attention output (pre out-proj)

// ---------------- simple fp32 SGEMM: C = A(MxK) @ B(KxN), row-major ---------
__global__ void sgemm(const float* __restrict__ A, const float* __restrict__ B,
                      float* __restrict__ Cmat, int M, int N, int K) {
    __shared__ float As[16][64];
    __shared__ float Bs[16][64];
    int tid = threadIdx.x;
    int m0 = blockIdx.y * 64, n0 = blockIdx.x * 64;
    int ty = tid >> 4, tx = tid & 15;
    int arow = tid >> 2;          // 0..63
    int acol = (tid & 3) * 4;     // 0..12
    int brow = tid >> 4;          // 0..15
    int bcol = (tid & 15) * 4;    // 0..60
    float acc[4][4];
#pragma unroll
    for (int i = 0; i < 4; i++)
#pragma unroll
        for (int j = 0; j < 4; j++) acc[i][j] = 0.f;

    for (int k0 = 0; k0 < K; k0 += 16) {
        int mm = m0 + arow;
#pragma unroll
        for (int j = 0; j < 4; j++) {
            int kk = k0 + acol + j;
            As[acol + j][arow] = (mm < M && kk < K) ? A[(size_t)mm * K + kk] : 0.f;
        }
        int kk = k0 + brow;
#pragma unroll
        for (int j = 0; j < 4; j++) {
            int nn = n0 + bcol + j;
            Bs[brow][bcol + j] = (kk < K && nn < N) ? B[(size_t)kk * N + nn] : 0.f;
        }
        __syncthreads();
#pragma unroll
        for (int k = 0; k < 16; k++) {
            float ra[4], rb[4];
#pragma unroll
            for (int i = 0; i < 4; i++) ra[i] = As[k][ty * 4 + i];
#pragma unroll
            for (int i = 0; i < 4; i++) rb[i] = Bs[k][tx * 4 + i];
#pragma unroll
            for (int i = 0; i < 4; i++)
#pragma unroll
                for (int j = 0; j < 4; j++) acc[i][j] += ra[i] * rb[j];
        }
        __syncthreads();
    }
#pragma unroll
    for (int i = 0; i < 4; i++) {
        int mm = m0 + ty * 4 + i;
        if (mm >= M) continue;
#pragma unroll
        for (int j = 0; j < 4; j++) {
            int nn = n0 + tx * 4 + j;
            if (nn < N) Cmat[(size_t)mm * N + nn] = acc[i][j];
        }
    }
}

// ---------------- time_att[b,h,t,p] = (q[t]+tb_h) . tk_h[p] ------------------
__global__ void time_att_kernel(const float* __restrict__ q,
                                const float* __restrict__ bias) {
    __shared__ float qs[32][65];
    __shared__ float tks[128][64];
    int bh = blockIdx.x;
    int b = bh / Hh, h = bh % Hh, kvh = h / Gg;
    int t0 = blockIdx.y * 32;
    int tid = threadIdx.x;
    for (int i = tid; i < 32 * 64; i += 256) {
        int r = i >> 6, d = i & 63;
        qs[r][d] = q[((size_t)(b * Tt + t0 + r)) * Ee + h * Dd + d]
                 + bias[EKVv + kvh * Dd + d];
    }
    for (int i = tid; i < 128 * 64; i += 256) {
        int p = i >> 6, d = i & 63;
        tks[p][d] = g_tk[p * EKVv + kvh * Dd + d];
    }
    __syncthreads();
    int r = tid & 31;
    int pb = (tid >> 5) * 16;
    float acc[16];
#pragma unroll
    for (int j = 0; j < 16; j++) acc[j] = 0.f;
    for (int d = 0; d < 64; d++) {
        float qv = qs[r][d];
#pragma unroll
        for (int j = 0; j < 16; j++) acc[j] += qv * tks[pb + j][d];
    }
    float* dst = g_time + ((size_t)bh * Tt + t0 + r) * Pp + pb;
#pragma unroll
    for (int j = 0; j < 16; j++) dst[j] = acc[j];
}

// ---------------- chan_att[b,h,t,c] = (q[t]+cb_h) . ck_h[c] ------------------
__global__ void chan_att_kernel(const float* __restrict__ q,
                                const float* __restrict__ bias) {
    __shared__ float qs[32][65];
    __shared__ float cks[8][65];
    int bh = blockIdx.x;
    int b = bh / Hh, h = bh % Hh, kvh = h / Gg;
    int t0 = blockIdx.y * 32;
    int tid = threadIdx.x;
    for (int i = tid; i < 32 * 64; i += 256) {
        int r = i >> 6, d = i & 63;
        qs[r][d] = q[((size_t)(b * Tt + t0 + r)) * Ee + h * Dd + d]
                 + bias[2 * EKVv + kvh * Dd + d];
    }
    // FIX (R1 bug): 8*64 = 512 elements but only 256 threads — loop, don't guard.
    for (int i = tid; i < 8 * 64; i += 256) {
        int c = i >> 6, d = i & 63;
        cks[c][d] = g_ck[c * EKVv + kvh * Dd + d];
    }
    __syncthreads();
    int r = tid >> 3, c = tid & 7;
    float acc = 0.f;
#pragma unroll
    for (int d = 0; d < 64; d++) acc += qs[r][d] * cks[c][d];
    g_chan[((size_t)bh * Tt + t0 + r) * Cc + c] = acc;
}

// ---------------- attention core: one block per (b, h, pt) -------------------
__global__ void attn_kernel(const float* __restrict__ q,
                            const float* __restrict__ bias) {
    __shared__ float qg[8][65];      // q + global bias
    __shared__ float lg[8][1025];    // logits -> exp weights
    __shared__ float rinv[8];
    int blk = blockIdx.x;
    int pt = blk % Pp;
    int h  = (blk / Pp) % Hh;
    int b  = blk / (Pp * Hh);
    int kvh = h / Gg;
    int tid = threadIdx.x;
    int t0 = pt * Cc;

    for (int i = tid; i < 8 * 64; i += 256) {
        int c = i >> 6, d = i & 63;
        qg[c][d] = q[((size_t)(b * Tt + t0 + c)) * Ee + h * Dd + d]
                 + bias[kvh * Dd + d];
    }
    __syncthreads();

    int S = (pt + 1) * Cc;                       // causal extent (patch-level)
    const float* tbase = g_time + (size_t)(b * Hh + h) * Tt * Pp;
    const float* cbase = g_chan + (size_t)(b * Hh + h) * Tt * Cc;

    // base logits: rel-shifted time + rel-shifted chan
    for (int idx = tid; idx < S * 8; idx += 256) {
        int s = idx >> 3, c = idx & 7;
        int t = t0 + c;
        int ps = s >> 3, cs = s & 7;
        int m = (t + 1) * Pp + ps;
        int i2 = m / (Tt + 1);
        float tv = 0.f;
        if (m - i2 * (Tt + 1) != 0) tv = tbase[m - i2 - 1];  // flat-index gather
        int dc = c - cs; dc = dc < 0 ? -dc : dc;
        float cv = cbase[t * Cc + (Cc - 1 - dc)];
        lg[c][s] = tv + cv;
    }
    __syncthreads();

    // global term only inside the wm band (last patch row: everywhere)
    int gLow = (pt == Pp - 1) ? 0 : ((pt > 10 ? pt - 10 : 0) * Cc);
    int nG = (S - gLow) * 8;
    for (int idx = tid; idx < nG; idx += 256) {
        int s = gLow + (idx >> 3);
        int c = idx & 7;
        const float4* gk4 = (const float4*)(g_kv
            + ((size_t)(b * Tt + s)) * (2 * EKVv) + kvh * Dd);
        float acc = 0.f;
#pragma unroll
        for (int d4 = 0; d4 < 16; d4++) {
            float4 gv = gk4[d4];
            acc += qg[c][d4 * 4 + 0] * gv.x + qg[c][d4 * 4 + 1] * gv.y
                 + qg[c][d4 * 4 + 2] * gv.z + qg[c][d4 * 4 + 3] * gv.w;
        }
        lg[c][s] += acc;
    }
    __syncthreads();

    // softmax: warp w owns row w (scale 1/sqrt(D)=0.125 applied here)
    int w = tid >> 5, lane = tid & 31;
    {
        float mx = -1e30f;
        for (int s = lane; s < S; s += 32) mx = fmaxf(mx, lg[w][s] * 0.125f);
#pragma unroll
        for (int o = 16; o > 0; o >>= 1)
            mx = fmaxf(mx, __shfl_xor_sync(0xffffffffu, mx, o));
        float sum = 0.f;
        for (int s = lane; s < S; s += 32) {
            float e = __expf(lg[w][s] * 0.125f - mx);
            lg[w][s] = e;
            sum += e;
        }
#pragma unroll
        for (int o = 16; o > 0; o >>= 1)
            sum += __shfl_xor_sync(0xffffffffu, sum, o);
        if (lane == 0) rinv[w] = 1.f / sum;
    }
    __syncthreads();

    // out[c,d] = sum_s w[c,s] * v[s,d]
    for (int idx = tid; idx < 8 * 64; idx += 256) {
        int c = idx >> 6, d = idx & 63;
        const float* vcol = g_kv + (size_t)b * Tt * (2 * EKVv) + EKVv + kvh * Dd + d;
        float acc = 0.f;
#pragma unroll 4
        for (int s = 0; s < S; s++) acc += lg[c][s] * vcol[(size_t)s * (2 * EKVv)];
        g_ao[((size_t)(b * Tt + t0 + c)) * Ee + h * Dd + d] = acc * rinv[c];
    }
}

// ---------------- launch ----------------------------------------------------
extern "C" void kernel_launch(void* const* d_in, const int* in_sizes, int n_in,
                              void* d_out, int out_size) {
    const float* hs    = (const float*)d_in[0];
    const float* pe    = (const float*)d_in[1];
    const float* ce    = (const float*)d_in[2];
    const float* Wq    = (const float*)d_in[3];
    const float* Wkv   = (const float*)d_in[4];
    const float* Wpos  = (const float*)d_in[5];
    const float* Wchan = (const float*)d_in[6];
    const float* Wproj = (const float*)d_in[7];
    const float* bias  = (const float*)d_in[8];

    float *q, *kv, *tk, *ck, *ao;
    cudaGetSymbolAddress((void**)&q,  g_q);
    cudaGetSymbolAddress((void**)&kv, g_kv);
    cudaGetSymbolAddress((void**)&tk, g_tk);
    cudaGetSymbolAddress((void**)&ck, g_ck);
    cudaGetSymbolAddress((void**)&ao, g_ao);

    // projections
    sgemm<<<dim3(Ee / 64, (Bb * Tt) / 64), 256>>>(hs, Wq, q, Bb * Tt, Ee, Ee);
    sgemm<<<dim3((2 * EKVv) / 64, (Bb * Tt) / 64), 256>>>(hs, Wkv, kv, Bb * Tt, 2 * EKVv, Ee);
    sgemm<<<dim3(EKVv / 64, Pp / 64), 256>>>(pe, Wpos, tk, Pp, EKVv, Ee);
    sgemm<<<dim3(EKVv / 64, 1), 256>>>(ce, Wchan, ck, Cc, EKVv, Ee);

    // relative logits
    time_att_kernel<<<dim3(Bb * Hh, Tt / 32), 256>>>(q, bias);
    chan_att_kernel<<<dim3(Bb * Hh, Tt / 32), 256>>>(q, bias);

    // attention core
    attn_kernel<<<Bb * Hh * Pp, 256>>>(q, bias);

    // output projection -> d_out
    sgemm<<<dim3(Ee / 64, (Bb * Tt) / 64), 256>>>(ao, Wproj, (float*)d_out, Bb * Tt, Ee, Ee);
}

// round 4
// speedup vs baseline: 1.1584x; 1.1584x over previous
#include <cuda_runtime.h>

#define Bb  2
#define Pp  128
#define Cc  8
#define Hh  16
#define Gg  4
#define Dd  64
#define Ee  1024
#define EKVv 256
#define Tt  1024

// ---------------- scratch (device globals; no allocation allowed) -----------
__device__ __align__(16) float g_q[Bb*Tt*Ee];          // [B,T,E]  q = hs @ Wq
__device__ __align__(16) float g_kv[Bb*Tt*2*EKVv];     // [B,T,512] gk | v
__device__ __align__(16) float g_tk[Pp*EKVv];          // pos_emb @ Wpos
__device__ __align__(16) float g_ck[Cc*EKVv];          // chan_emb @ Wchan
__device__ __align__(16) float g_time[Bb*Hh*Tt*Pp];    // time_att (pre-shift)
__device__ __align__(16) float g_chan[Bb*Hh*Tt*Cc];    // chan_att (pre-shift)
__device__ __align__(16) float g_ao[Bb*Tt*Ee];         // attention output

// ------------- fast fp32 SGEMM: C = A(MxK)@B(KxN), 128x128 tile, 8x8/thread --
// Requires: M%128==0, N%128==0, K%8==0, 16B-aligned pointers. No bounds checks.
__global__ __launch_bounds__(256) void sgemm128(
        const float* __restrict__ A, const float* __restrict__ B,
        float* __restrict__ Cmat, int M, int N, int K) {
    __shared__ float As[2][8][128];
    __shared__ float Bs[2][8][128];
    int tid = threadIdx.x;
    int m0 = blockIdx.y * 128, n0 = blockIdx.x * 128;
    int tx = tid & 15, ty = tid >> 4;

    // A loader: row = tid>>1 (0..127), kq = (tid&1)*4
    int arow = tid >> 1, akq = (tid & 1) * 4;
    // B loader: row = tid>>5 (0..7), nq = (tid&31)*4
    int brow = tid >> 5, bnq = (tid & 31) * 4;

    const float* Aptr = A + (size_t)(m0 + arow) * K + akq;
    const float* Bptr = B + (size_t)brow * N + n0 + bnq;

    float acc[8][8];
#pragma unroll
    for (int i = 0; i < 8; i++)
#pragma unroll
        for (int j = 0; j < 8; j++) acc[i][j] = 0.f;

    // preload tile 0
    float4 av = *(const float4*)Aptr;
    float4 bv = *(const float4*)Bptr;
    As[0][akq + 0][arow] = av.x;
    As[0][akq + 1][arow] = av.y;
    As[0][akq + 2][arow] = av.z;
    As[0][akq + 3][arow] = av.w;
    *(float4*)&Bs[0][brow][bnq] = bv;
    __syncthreads();

    int NT = K >> 3;
    int cur = 0;
    for (int kt = 0; kt < NT; kt++) {
        if (kt + 1 < NT) {
            av = *(const float4*)(Aptr + (kt + 1) * 8);
            bv = *(const float4*)(Bptr + (size_t)(kt + 1) * 8 * N);
        }
#pragma unroll
        for (int k = 0; k < 8; k++) {
            float4 a0 = *(const float4*)&As[cur][k][ty * 8];
            float4 a1 = *(const float4*)&As[cur][k][ty * 8 + 4];
            float4 b0 = *(const float4*)&Bs[cur][k][tx * 8];
            float4 b1 = *(const float4*)&Bs[cur][k][tx * 8 + 4];
            float ra[8] = {a0.x, a0.y, a0.z, a0.w, a1.x, a1.y, a1.z, a1.w};
            float rb[8] = {b0.x, b0.y, b0.z, b0.w, b1.x, b1.y, b1.z, b1.w};
#pragma unroll
            for (int i = 0; i < 8; i++)
#pragma unroll
                for (int j = 0; j < 8; j++) acc[i][j] += ra[i] * rb[j];
        }
        if (kt + 1 < NT) {
            int nxt = cur ^ 1;
            As[nxt][akq + 0][arow] = av.x;
            As[nxt][akq + 1][arow] = av.y;
            As[nxt][akq + 2][arow] = av.z;
            As[nxt][akq + 3][arow] = av.w;
            *(float4*)&Bs[nxt][brow][bnq] = bv;
            __syncthreads();
            cur = nxt;
        }
    }

#pragma unroll
    for (int i = 0; i < 8; i++) {
        float* crow = Cmat + (size_t)(m0 + ty * 8 + i) * N + n0 + tx * 8;
        float4 c0 = {acc[i][0], acc[i][1], acc[i][2], acc[i][3]};
        float4 c1 = {acc[i][4], acc[i][5], acc[i][6], acc[i][7]};
        *(float4*)crow = c0;
        *(float4*)(crow + 4) = c1;
    }
}

// ------------- skinny GEMM (tiny M): grid = (N/128, M), 128 threads ---------
__global__ void skinny_gemm(const float* __restrict__ A, const float* __restrict__ B,
                            float* __restrict__ C, int N, int K) {
    __shared__ float As[128];
    int m = blockIdx.y;
    int n = blockIdx.x * 128 + threadIdx.x;
    float acc = 0.f;
    for (int k0 = 0; k0 < K; k0 += 128) {
        __syncthreads();
        As[threadIdx.x] = A[(size_t)m * K + k0 + threadIdx.x];
        __syncthreads();
#pragma unroll 32
        for (int kk = 0; kk < 128; kk++)
            acc += As[kk] * B[(size_t)(k0 + kk) * N + n];
    }
    C[(size_t)m * N + n] = acc;
}

// ---------------- time_att[b,h,t,p] = (q[t]+tb_h) . tk_h[p] ------------------
__global__ void time_att_kernel(const float* __restrict__ q,
                                const float* __restrict__ bias) {
    __shared__ float qs[32][65];
    __shared__ float tks[128][64];
    int bh = blockIdx.x;
    int b = bh / Hh, h = bh % Hh, kvh = h / Gg;
    int t0 = blockIdx.y * 32;
    int tid = threadIdx.x;
    for (int i = tid; i < 32 * 64; i += 256) {
        int r = i >> 6, d = i & 63;
        qs[r][d] = q[((size_t)(b * Tt + t0 + r)) * Ee + h * Dd + d]
                 + bias[EKVv + kvh * Dd + d];
    }
    for (int i = tid; i < 128 * 64; i += 256) {
        int p = i >> 6, d = i & 63;
        tks[p][d] = g_tk[p * EKVv + kvh * Dd + d];
    }
    __syncthreads();
    int r = tid & 31;
    int pb = (tid >> 5) * 16;
    float acc[16];
#pragma unroll
    for (int j = 0; j < 16; j++) acc[j] = 0.f;
    for (int d = 0; d < 64; d++) {
        float qv = qs[r][d];
#pragma unroll
        for (int j = 0; j < 16; j++) acc[j] += qv * tks[pb + j][d];
    }
    float* dst = g_time + ((size_t)bh * Tt + t0 + r) * Pp + pb;
#pragma unroll
    for (int j = 0; j < 16; j++) dst[j] = acc[j];
}

// ---------------- chan_att[b,h,t,c] = (q[t]+cb_h) . ck_h[c] ------------------
__global__ void chan_att_kernel(const float* __restrict__ q,
                                const float* __restrict__ bias) {
    __shared__ float qs[32][65];
    __shared__ float cks[8][65];
    int bh = blockIdx.x;
    int b = bh / Hh, h = bh % Hh, kvh = h / Gg;
    int t0 = blockIdx.y * 32;
    int tid = threadIdx.x;
    for (int i = tid; i < 32 * 64; i += 256) {
        int r = i >> 6, d = i & 63;
        qs[r][d] = q[((size_t)(b * Tt + t0 + r)) * Ee + h * Dd + d]
                 + bias[2 * EKVv + kvh * Dd + d];
    }
    for (int i = tid; i < 8 * 64; i += 256) {
        int c = i >> 6, d = i & 63;
        cks[c][d] = g_ck[c * EKVv + kvh * Dd + d];
    }
    __syncthreads();
    int r = tid >> 3, c = tid & 7;
    float acc = 0.f;
#pragma unroll
    for (int d = 0; d < 64; d++) acc += qs[r][d] * cks[c][d];
    g_chan[((size_t)bh * Tt + t0 + r) * Cc + c] = acc;
}

// ---------------- attention core: one block per (b, h, pt) -------------------
__global__ void attn_kernel(const float* __restrict__ q,
                            const float* __restrict__ bias) {
    __shared__ float qg[8][65];      // q + global bias
    __shared__ float lg[8][1025];    // logits -> exp weights
    __shared__ float rinv[8];
    int blk = blockIdx.x;
    int pt = blk % Pp;
    int h  = (blk / Pp) % Hh;
    int b  = blk / (Pp * Hh);
    int kvh = h / Gg;
    int tid = threadIdx.x;
    int t0 = pt * Cc;

    for (int i = tid; i < 8 * 64; i += 256) {
        int c = i >> 6, d = i & 63;
        qg[c][d] = q[((size_t)(b * Tt + t0 + c)) * Ee + h * Dd + d]
                 + bias[kvh * Dd + d];
    }
    __syncthreads();

    int S = (pt + 1) * Cc;                       // causal extent (patch-level)
    const float* tbase = g_time + (size_t)(b * Hh + h) * Tt * Pp;
    const float* cbase = g_chan + (size_t)(b * Hh + h) * Tt * Cc;

    // base logits: rel-shifted time + rel-shifted chan
    for (int idx = tid; idx < S * 8; idx += 256) {
        int s = idx >> 3, c = idx & 7;
        int t = t0 + c;
        int ps = s >> 3, cs = s & 7;
        int m = (t + 1) * Pp + ps;
        int i2 = m / (Tt + 1);
        float tv = 0.f;
        if (m - i2 * (Tt + 1) != 0) tv = tbase[m - i2 - 1];  // flat-index gather
        int dc = c - cs; dc = dc < 0 ? -dc : dc;
        float cv = cbase[t * Cc + (Cc - 1 - dc)];
        lg[c][s] = tv + cv;
    }
    __syncthreads();

    // global term only inside the wm band (last patch row: everywhere)
    int gLow = (pt == Pp - 1) ? 0 : ((pt > 10 ? pt - 10 : 0) * Cc);
    int nG = (S - gLow) * 8;
    for (int idx = tid; idx < nG; idx += 256) {
        int s = gLow + (idx >> 3);
        int c = idx & 7;
        const float4* gk4 = (const float4*)(g_kv
            + ((size_t)(b * Tt + s)) * (2 * EKVv) + kvh * Dd);
        float acc = 0.f;
#pragma unroll
        for (int d4 = 0; d4 < 16; d4++) {
            float4 gv = gk4[d4];
            acc += qg[c][d4 * 4 + 0] * gv.x + qg[c][d4 * 4 + 1] * gv.y
                 + qg[c][d4 * 4 + 2] * gv.z + qg[c][d4 * 4 + 3] * gv.w;
        }
        lg[c][s] += acc;
    }
    __syncthreads();

    // softmax: warp w owns row w (scale 1/sqrt(D)=0.125 applied here)
    int w = tid >> 5, lane = tid & 31;
    {
        float mx = -1e30f;
        for (int s = lane; s < S; s += 32) mx = fmaxf(mx, lg[w][s] * 0.125f);
#pragma unroll
        for (int o = 16; o > 0; o >>= 1)
            mx = fmaxf(mx, __shfl_xor_sync(0xffffffffu, mx, o));
        float sum = 0.f;
        for (int s = lane; s < S; s += 32) {
            float e = __expf(lg[w][s] * 0.125f - mx);
            lg[w][s] = e;
            sum += e;
        }
#pragma unroll
        for (int o = 16; o > 0; o >>= 1)
            sum += __shfl_xor_sync(0xffffffffu, sum, o);
        if (lane == 0) rinv[w] = 1.f / sum;
    }
    __syncthreads();

    // out[c,d] = sum_s w[c,s] * v[s,d]
    for (int idx = tid; idx < 8 * 64; idx += 256) {
        int c = idx >> 6, d = idx & 63;
        const float* vcol = g_kv + (size_t)b * Tt * (2 * EKVv) + EKVv + kvh * Dd + d;
        float acc = 0.f;
#pragma unroll 4
        for (int s = 0; s < S; s++) acc += lg[c][s] * vcol[(size_t)s * (2 * EKVv)];
        g_ao[((size_t)(b * Tt + t0 + c)) * Ee + h * Dd + d] = acc * rinv[c];
    }
}

// ---------------- launch ----------------------------------------------------
extern "C" void kernel_launch(void* const* d_in, const int* in_sizes, int n_in,
                              void* d_out, int out_size) {
    const float* hs    = (const float*)d_in[0];
    const float* pe    = (const float*)d_in[1];
    const float* ce    = (const float*)d_in[2];
    const float* Wq    = (const float*)d_in[3];
    const float* Wkv   = (const float*)d_in[4];
    const float* Wpos  = (const float*)d_in[5];
    const float* Wchan = (const float*)d_in[6];
    const float* Wproj = (const float*)d_in[7];
    const float* bias  = (const float*)d_in[8];

    float *q, *kv, *tk, *ck, *ao;
    cudaGetSymbolAddress((void**)&q,  g_q);
    cudaGetSymbolAddress((void**)&kv, g_kv);
    cudaGetSymbolAddress((void**)&tk, g_tk);
    cudaGetSymbolAddress((void**)&ck, g_ck);
    cudaGetSymbolAddress((void**)&ao, g_ao);

    // projections (M,N multiples of 128; K=1024)
    sgemm128<<<dim3(Ee / 128, (Bb * Tt) / 128), 256>>>(hs, Wq, q, Bb * Tt, Ee, Ee);
    sgemm128<<<dim3((2 * EKVv) / 128, (Bb * Tt) / 128), 256>>>(hs, Wkv, kv, Bb * Tt, 2 * EKVv, Ee);

    // skinny projections (M = 128 / 8)
    skinny_gemm<<<dim3(EKVv / 128, Pp), 128>>>(pe, Wpos, tk, EKVv, Ee);
    skinny_gemm<<<dim3(EKVv / 128, Cc), 128>>>(ce, Wchan, ck, EKVv, Ee);

    // relative logits
    time_att_kernel<<<dim3(Bb * Hh, Tt / 32), 256>>>(q, bias);
    chan_att_kernel<<<dim3(Bb * Hh, Tt / 32), 256>>>(q, bias);

    // attention core
    attn_kernel<<<Bb * Hh * Pp, 256>>>(q, bias);

    // output projection -> d_out
    sgemm128<<<dim3(Ee / 128, (Bb * Tt) / 128), 256>>>(ao, Wproj, (float*)d_out, Bb * Tt, Ee, Ee);
}

// round 5
// speedup vs baseline: 2.2006x; 1.8997x over previous
#include <cuda_runtime.h>

#define Bb  2
#define Pp  128
#define Cc  8
#define Hh  16
#define Gg  4
#define Dd  64
#define Ee  1024
#define EKVv 256
#define Tt  1024

// ---------------- scratch (device globals; no allocation allowed) -----------
__device__ __align__(16) float g_q[Bb*Tt*Ee];          // [B,T,E]  q = hs @ Wq
__device__ __align__(16) float g_kv[Bb*Tt*2*EKVv];     // [B,T,512] gk | v
__device__ __align__(16) float g_tk[Pp*EKVv];          // pos_emb @ Wpos
__device__ __align__(16) float g_ck[Cc*EKVv];          // chan_emb @ Wchan
__device__ __align__(16) float g_time[Bb*Hh*Tt*Pp];    // time_att (pre-shift)
__device__ __align__(16) float g_chan[Bb*Hh*Tt*Cc];    // chan_att (pre-shift)
__device__ __align__(16) float g_ao[Bb*Tt*Ee];         // attention output

// ---------------- 128x128 fp32 GEMM tile body (8x8/thread, dbl-buffered) ----
// C[m0:+128, n0:+128] = A(MxK) @ B(KxN). K%8==0, rows 16B-aligned.
__device__ __forceinline__ void gemm128_body(
        const float* __restrict__ A, const float* __restrict__ B,
        float* __restrict__ Cmat, int N, int K, int m0, int n0,
        float (*As)[8][128], float (*Bs)[8][128]) {
    int tid = threadIdx.x;
    int tx = tid & 15, ty = tid >> 4;
    int arow = tid >> 1, akq = (tid & 1) * 4;
    int brow = tid >> 5, bnq = (tid & 31) * 4;

    const float* Aptr = A + (size_t)(m0 + arow) * K + akq;
    const float* Bptr = B + (size_t)brow * N + n0 + bnq;

    float acc[8][8];
#pragma unroll
    for (int i = 0; i < 8; i++)
#pragma unroll
        for (int j = 0; j < 8; j++) acc[i][j] = 0.f;

    float4 av = *(const float4*)Aptr;
    float4 bv = *(const float4*)Bptr;
    As[0][akq + 0][arow] = av.x;
    As[0][akq + 1][arow] = av.y;
    As[0][akq + 2][arow] = av.z;
    As[0][akq + 3][arow] = av.w;
    *(float4*)&Bs[0][brow][bnq] = bv;
    __syncthreads();

    int NT = K >> 3;
    int cur = 0;
    for (int kt = 0; kt < NT; kt++) {
        if (kt + 1 < NT) {
            av = *(const float4*)(Aptr + (kt + 1) * 8);
            bv = *(const float4*)(Bptr + (size_t)(kt + 1) * 8 * N);
        }
#pragma unroll
        for (int k = 0; k < 8; k++) {
            float4 a0 = *(const float4*)&As[cur][k][ty * 8];
            float4 a1 = *(const float4*)&As[cur][k][ty * 8 + 4];
            float4 b0 = *(const float4*)&Bs[cur][k][tx * 8];
            float4 b1 = *(const float4*)&Bs[cur][k][tx * 8 + 4];
            float ra[8] = {a0.x, a0.y, a0.z, a0.w, a1.x, a1.y, a1.z, a1.w};
            float rb[8] = {b0.x, b0.y, b0.z, b0.w, b1.x, b1.y, b1.z, b1.w};
#pragma unroll
            for (int i = 0; i < 8; i++)
#pragma unroll
                for (int j = 0; j < 8; j++) acc[i][j] += ra[i] * rb[j];
        }
        if (kt + 1 < NT) {
            int nxt = cur ^ 1;
            As[nxt][akq + 0][arow] = av.x;
            As[nxt][akq + 1][arow] = av.y;
            As[nxt][akq + 2][arow] = av.z;
            As[nxt][akq + 3][arow] = av.w;
            *(float4*)&Bs[nxt][brow][bnq] = bv;
            __syncthreads();
            cur = nxt;
        }
    }

#pragma unroll
    for (int i = 0; i < 8; i++) {
        float* crow = Cmat + (size_t)(m0 + ty * 8 + i) * N + n0 + tx * 8;
        float4 c0 = {acc[i][0], acc[i][1], acc[i][2], acc[i][3]};
        float4 c1 = {acc[i][4], acc[i][5], acc[i][6], acc[i][7]};
        *(float4*)crow = c0;
        *(float4*)(crow + 4) = c1;
    }
}

// ---------------- skinny row GEMM: C[m, n0:+128], intra-block split-K --------
__device__ __forceinline__ void skinny_body(
        const float* __restrict__ A, const float* __restrict__ B,
        float* __restrict__ C, int N, int K, int m, int n0) {
    __shared__ float red[128];
    int t = threadIdx.x;
    int n = n0 + (t & 127);
    int kc = t >> 7;                 // 0 or 1; each half does K/2
    int kh = K >> 1;
    const float* a = A + (size_t)m * K + kc * kh;
    const float* b = B + (size_t)(kc * kh) * N + n;
    float acc = 0.f;
#pragma unroll 8
    for (int k = 0; k < kh; k++) acc += a[k] * b[(size_t)k * N];
    if (kc) red[t & 127] = acc;
    __syncthreads();
    if (!kc) C[(size_t)m * N + n] = acc + red[t & 127];
}

// ---------------- one launch for ALL projections (fills the chip) ------------
// blocks: [0,128) q | [128,192) kv | [192,448) tk | [448,464) ck
__global__ __launch_bounds__(256) void mega_gemm(
        const float* __restrict__ hs, const float* __restrict__ Wq,
        const float* __restrict__ Wkv,
        const float* __restrict__ pe, const float* __restrict__ Wpos,
        const float* __restrict__ ce, const float* __restrict__ Wchan,
        float* __restrict__ q, float* __restrict__ kv,
        float* __restrict__ tk, float* __restrict__ ck) {
    __shared__ float As[2][8][128];
    __shared__ float Bs[2][8][128];
    int blk = blockIdx.x;
    if (blk < 128) {
        gemm128_body(hs, Wq, q, Ee, Ee, (blk >> 3) * 128, (blk & 7) * 128, As, Bs);
    } else if (blk < 192) {
        int b = blk - 128;
        gemm128_body(hs, Wkv, kv, 2 * EKVv, Ee, (b >> 2) * 128, (b & 3) * 128, As, Bs);
    } else if (blk < 448) {
        int b = blk - 192;
        skinny_body(pe, Wpos, tk, EKVv, Ee, b >> 1, (b & 1) * 128);
    } else {
        int b = blk - 448;
        skinny_body(ce, Wchan, ck, EKVv, Ee, b >> 1, (b & 1) * 128);
    }
}

// ---------------- standalone GEMM for the output projection ------------------
__global__ __launch_bounds__(256) void sgemm128(
        const float* __restrict__ A, const float* __restrict__ B,
        float* __restrict__ Cmat, int N, int K) {
    __shared__ float As[2][8][128];
    __shared__ float Bs[2][8][128];
    gemm128_body(A, B, Cmat, N, K, blockIdx.y * 128, blockIdx.x * 128, As, Bs);
}

// ---------------- merged time_att + chan_att ---------------------------------
// blocks [0,1024): time (bh = blk%32, t0 = (blk/32)*32)
// blocks [1024,2048): chan
__global__ __launch_bounds__(256) void rel_att_kernel(
        const float* __restrict__ q, const float* __restrict__ bias) {
    __shared__ float qs[32][65];
    __shared__ float ks[128][64];
    int blk = blockIdx.x;
    int tid = threadIdx.x;
    if (blk < 1024) {
        int bh = blk & 31;
        int b = bh / Hh, h = bh % Hh, kvh = h / Gg;
        int t0 = (blk >> 5) * 32;
        for (int i = tid; i < 32 * 64; i += 256) {
            int r = i >> 6, d = i & 63;
            qs[r][d] = q[((size_t)(b * Tt + t0 + r)) * Ee + h * Dd + d]
                     + bias[EKVv + kvh * Dd + d];
        }
        for (int i = tid; i < 128 * 64; i += 256) {
            int p = i >> 6, d = i & 63;
            ks[p][d] = g_tk[p * EKVv + kvh * Dd + d];
        }
        __syncthreads();
        int r = tid & 31;
        int pb = (tid >> 5) * 16;
        float acc[16];
#pragma unroll
        for (int j = 0; j < 16; j++) acc[j] = 0.f;
        for (int d = 0; d < 64; d++) {
            float qv = qs[r][d];
#pragma unroll
            for (int j = 0; j < 16; j++) acc[j] += qv * ks[pb + j][d];
        }
        float* dst = g_time + ((size_t)bh * Tt + t0 + r) * Pp + pb;
#pragma unroll
        for (int j = 0; j < 16; j++) dst[j] = acc[j];
    } else {
        int bc = blk - 1024;
        int bh = bc & 31;
        int b = bh / Hh, h = bh % Hh, kvh = h / Gg;
        int t0 = (bc >> 5) * 32;
        for (int i = tid; i < 32 * 64; i += 256) {
            int r = i >> 6, d = i & 63;
            qs[r][d] = q[((size_t)(b * Tt + t0 + r)) * Ee + h * Dd + d]
                     + bias[2 * EKVv + kvh * Dd + d];
        }
        for (int i = tid; i < 8 * 64; i += 256) {
            int c = i >> 6, d = i & 63;
            ks[c][d] = g_ck[c * EKVv + kvh * Dd + d];
        }
        __syncthreads();
        int r = tid >> 3, c = tid & 7;
        float acc = 0.f;
#pragma unroll
        for (int d = 0; d < 64; d++) acc += qs[r][d] * ks[c][d];
        g_chan[((size_t)bh * Tt + t0 + r) * Cc + c] = acc;
    }
}

// ---------------- attention core: one block per (b, h, pt) -------------------
__global__ __launch_bounds__(256) void attn_kernel(
        const float* __restrict__ q, const float* __restrict__ bias) {
    __shared__ float qg[8][65];      // q + global bias
    __shared__ float lg[8][1025];    // logits -> exp weights
    __shared__ float rinv[8];
    __shared__ float sred[8][8][64]; // [sgroup][c][d] partials
    int blk = blockIdx.x;
    int pt = blk % Pp;
    int h  = (blk / Pp) % Hh;
    int b  = blk / (Pp * Hh);
    int kvh = h / Gg;
    int tid = threadIdx.x;
    int t0 = pt * Cc;

    for (int i = tid; i < 8 * 64; i += 256) {
        int c = i >> 6, d = i & 63;
        qg[c][d] = q[((size_t)(b * Tt + t0 + c)) * Ee + h * Dd + d]
                 + bias[kvh * Dd + d];
    }
    __syncthreads();

    int S = (pt + 1) * Cc;                       // causal extent (patch-level)
    const float* tbase = g_time + (size_t)(b * Hh + h) * Tt * Pp;
    const float* cbase = g_chan + (size_t)(b * Hh + h) * Tt * Cc;

    // base logits: rel-shifted time + rel-shifted chan
    for (int idx = tid; idx < S * 8; idx += 256) {
        int s = idx >> 3, c = idx & 7;
        int t = t0 + c;
        int ps = s >> 3, cs = s & 7;
        unsigned m = (unsigned)(t + 1) * Pp + ps;
        unsigned i2 = m / (Tt + 1);
        float tv = 0.f;
        if (m - i2 * (Tt + 1) != 0) tv = tbase[m - i2 - 1];  // flat-index gather
        int dc = c - cs; dc = dc < 0 ? -dc : dc;
        float cv = cbase[t * Cc + (Cc - 1 - dc)];
        lg[c][s] = tv + cv;
    }
    __syncthreads();

    // global term only inside the wm band (last patch row: everywhere)
    int gLow = (pt == Pp - 1) ? 0 : ((pt > 10 ? pt - 10 : 0) * Cc);
    int nG = (S - gLow) * 8;
    for (int idx = tid; idx < nG; idx += 256) {
        int s = gLow + (idx >> 3);
        int c = idx & 7;
        const float4* gk4 = (const float4*)(g_kv
            + ((size_t)(b * Tt + s)) * (2 * EKVv) + kvh * Dd);
        float acc = 0.f;
#pragma unroll
        for (int d4 = 0; d4 < 16; d4++) {
            float4 gv = gk4[d4];
            acc += qg[c][d4 * 4 + 0] * gv.x + qg[c][d4 * 4 + 1] * gv.y
                 + qg[c][d4 * 4 + 2] * gv.z + qg[c][d4 * 4 + 3] * gv.w;
        }
        lg[c][s] += acc;
    }
    __syncthreads();

    // softmax: warp w owns row w (scale 1/sqrt(D)=0.125 applied here)
    int w = tid >> 5, lane = tid & 31;
    {
        float mx = -1e30f;
        for (int s = lane; s < S; s += 32) mx = fmaxf(mx, lg[w][s] * 0.125f);
#pragma unroll
        for (int o = 16; o > 0; o >>= 1)
            mx = fmaxf(mx, __shfl_xor_sync(0xffffffffu, mx, o));
        float sum = 0.f;
        for (int s = lane; s < S; s += 32) {
            float e = __expf(lg[w][s] * 0.125f - mx);
            lg[w][s] = e;
            sum += e;
        }
#pragma unroll
        for (int o = 16; o > 0; o >>= 1)
            sum += __shfl_xor_sync(0xffffffffu, sum, o);
        if (lane == 0) rinv[w] = 1.f / sum;
    }
    __syncthreads();

    // out[c,d] = sum_s w[c,s]*v[s,d]; thread = (sgroup, d-pair), v loaded ONCE
    // per (s, d-pair) and reused for all 8 c rows (16 FMA per 8B LDG).
    {
        int dp = (tid & 31) * 2;     // d, d+1
        int sg = tid >> 5;           // 0..7
        const float* vbase = g_kv + (size_t)b * Tt * (2 * EKVv) + EKVv
                           + kvh * Dd + dp;
        float accx[8], accy[8];
#pragma unroll
        for (int c = 0; c < 8; c++) { accx[c] = 0.f; accy[c] = 0.f; }
        for (int s = sg; s < S; s += 8) {
            float2 vv = *(const float2*)(vbase + (size_t)s * (2 * EKVv));
#pragma unroll
            for (int c = 0; c < 8; c++) {
                float wgt = lg[c][s];
                accx[c] += wgt * vv.x;
                accy[c] += wgt * vv.y;
            }
        }
#pragma unroll
        for (int c = 0; c < 8; c++) {
            sred[sg][c][dp]     = accx[c];
            sred[sg][c][dp + 1] = accy[c];
        }
    }
    __syncthreads();
    for (int i = tid; i < 512; i += 256) {
        int c = i >> 6, dd = i & 63;
        float o = ((sred[0][c][dd] + sred[1][c][dd])
                 + (sred[2][c][dd] + sred[3][c][dd]))
                + ((sred[4][c][dd] + sred[5][c][dd])
                 + (sred[6][c][dd] + sred[7][c][dd]));
        g_ao[((size_t)(b * Tt + t0 + c)) * Ee + h * Dd + dd] = o * rinv[c];
    }
}

// ---------------- launch ----------------------------------------------------
extern "C" void kernel_launch(void* const* d_in, const int* in_sizes, int n_in,
                              void* d_out, int out_size) {
    const float* hs    = (const float*)d_in[0];
    const float* pe    = (const float*)d_in[1];
    const float* ce    = (const float*)d_in[2];
    const float* Wq    = (const float*)d_in[3];
    const float* Wkv   = (const float*)d_in[4];
    const float* Wpos  = (const float*)d_in[5];
    const float* Wchan = (const float*)d_in[6];
    const float* Wproj = (const float*)d_in[7];
    const float* bias  = (const float*)d_in[8];

    float *q, *kv, *tk, *ck, *ao;
    cudaGetSymbolAddress((void**)&q,  g_q);
    cudaGetSymbolAddress((void**)&kv, g_kv);
    cudaGetSymbolAddress((void**)&tk, g_tk);
    cudaGetSymbolAddress((void**)&ck, g_ck);
    cudaGetSymbolAddress((void**)&ao, g_ao);

    // all projections in one chip-filling launch
    mega_gemm<<<464, 256>>>(hs, Wq, Wkv, pe, Wpos, ce, Wchan, q, kv, tk, ck);

    // relative logits (time + chan merged)
    rel_att_kernel<<<2048, 256>>>(q, bias);

    // attention core
    attn_kernel<<<Bb * Hh * Pp, 256>>>(q, bias);

    // output projection -> d_out
    sgemm128<<<dim3(Ee / 128, (Bb * Tt) / 128), 256>>>(ao, Wproj, (float*)d_out, Ee, Ee);
}

// round 6
// speedup vs baseline: 2.2872x; 1.0394x over previous
#include <cuda_runtime.h>

#define Bb  2
#define Pp  128
#define Cc  8
#define Hh  16
#define Gg  4
#define Dd  64
#define Ee  1024
#define EKVv 256
#define Tt  1024

// ---------------- scratch (device globals; no allocation allowed) -----------
__device__ __align__(16) float g_q[Bb*Tt*Ee];          // [B,T,E]  q = hs @ Wq
__device__ __align__(16) float g_kv[Bb*Tt*2*EKVv];     // [B,T,512] gk | v
__device__ __align__(16) float g_tk[Pp*EKVv];          // pos_emb @ Wpos
__device__ __align__(16) float g_ck[Cc*EKVv];          // chan_emb @ Wchan
__device__ __align__(16) float g_time[Bb*Hh*Tt*Pp];    // time_att (pre-shift)
__device__ __align__(16) float g_chan[Bb*Hh*Tt*Cc];    // chan_att (pre-shift)
__device__ __align__(16) float g_ao[Bb*Tt*Ee];         // attention output

// ---------------- packed f32x2 helpers (sm_100+ PTX) -------------------------
__device__ __forceinline__ unsigned long long dup2(float x) {
    unsigned long long r;
    asm("mov.b64 %0, {%1, %1};" : "=l"(r) : "f"(x));
    return r;
}
__device__ __forceinline__ void fma2(unsigned long long& d,
                                     unsigned long long a, unsigned long long b) {
    asm("fma.rn.f32x2 %0, %1, %2, %0;" : "+l"(d) : "l"(a), "l"(b));
}

// ---------------- 128x128 fp32 GEMM tile body (8x8/thread, FMA2) -------------
// C[m0:+128, n0:+128] = A(MxK) @ B(KxN). K%8==0, rows 16B-aligned.
__device__ __forceinline__ void gemm128_body(
        const float* __restrict__ A, const float* __restrict__ B,
        float* __restrict__ Cmat, int N, int K, int m0, int n0,
        float (*As)[8][128], float (*Bs)[8][128]) {
    int tid = threadIdx.x;
    int tx = tid & 15, ty = tid >> 4;
    int arow = tid >> 1, akq = (tid & 1) * 4;
    int brow = tid >> 5, bnq = (tid & 31) * 4;

    const float* Aptr = A + (size_t)(m0 + arow) * K + akq;
    const float* Bptr = B + (size_t)brow * N + n0 + bnq;

    unsigned long long acc2[8][4];
#pragma unroll
    for (int i = 0; i < 8; i++)
#pragma unroll
        for (int j = 0; j < 4; j++) acc2[i][j] = 0ull;   // (0.f, 0.f)

    float4 av = *(const float4*)Aptr;
    float4 bv = *(const float4*)Bptr;
    As[0][akq + 0][arow] = av.x;
    As[0][akq + 1][arow] = av.y;
    As[0][akq + 2][arow] = av.z;
    As[0][akq + 3][arow] = av.w;
    *(float4*)&Bs[0][brow][bnq] = bv;
    __syncthreads();

    int NT = K >> 3;
    int cur = 0;
    for (int kt = 0; kt < NT; kt++) {
        if (kt + 1 < NT) {
            av = *(const float4*)(Aptr + (kt + 1) * 8);
            bv = *(const float4*)(Bptr + (size_t)(kt + 1) * 8 * N);
        }
#pragma unroll
        for (int k = 0; k < 8; k++) {
            float4 a0 = *(const float4*)&As[cur][k][ty * 8];
            float4 a1 = *(const float4*)&As[cur][k][ty * 8 + 4];
            ulonglong2 bl0 = *(const ulonglong2*)&Bs[cur][k][tx * 8];
            ulonglong2 bl1 = *(const ulonglong2*)&Bs[cur][k][tx * 8 + 4];
            float ra[8] = {a0.x, a0.y, a0.z, a0.w, a1.x, a1.y, a1.z, a1.w};
            unsigned long long rb2[4] = {bl0.x, bl0.y, bl1.x, bl1.y};
#pragma unroll
            for (int i = 0; i < 8; i++) {
                unsigned long long a2 = dup2(ra[i]);
#pragma unroll
                for (int j = 0; j < 4; j++) fma2(acc2[i][j], a2, rb2[j]);
            }
        }
        if (kt + 1 < NT) {
            int nxt = cur ^ 1;
            As[nxt][akq + 0][arow] = av.x;
            As[nxt][akq + 1][arow] = av.y;
            As[nxt][akq + 2][arow] = av.z;
            As[nxt][akq + 3][arow] = av.w;
            *(float4*)&Bs[nxt][brow][bnq] = bv;
            __syncthreads();
            cur = nxt;
        }
    }

#pragma unroll
    for (int i = 0; i < 8; i++) {
        float* crow = Cmat + (size_t)(m0 + ty * 8 + i) * N + n0 + tx * 8;
        *(ulonglong2*)crow       = make_ulonglong2(acc2[i][0], acc2[i][1]);
        *(ulonglong2*)(crow + 4) = make_ulonglong2(acc2[i][2], acc2[i][3]);
    }
}

// ---------------- skinny row GEMM: C[m, n0:+128], intra-block split-K --------
__device__ __forceinline__ void skinny_body(
        const float* __restrict__ A, const float* __restrict__ B,
        float* __restrict__ C, int N, int K, int m, int n0) {
    __shared__ float red[128];
    int t = threadIdx.x;
    int n = n0 + (t & 127);
    int kc = t >> 7;                 // 0 or 1; each half does K/2
    int kh = K >> 1;
    const float* a = A + (size_t)m * K + kc * kh;
    const float* b = B + (size_t)(kc * kh) * N + n;
    float acc = 0.f;
#pragma unroll 8
    for (int k = 0; k < kh; k++) acc += a[k] * b[(size_t)k * N];
    if (kc) red[t & 127] = acc;
    __syncthreads();
    if (!kc) C[(size_t)m * N + n] = acc + red[t & 127];
}

// ---------------- one launch for ALL projections (fills the chip) ------------
// blocks: [0,128) q | [128,192) kv | [192,448) tk | [448,464) ck
__global__ __launch_bounds__(256) void mega_gemm(
        const float* __restrict__ hs, const float* __restrict__ Wq,
        const float* __restrict__ Wkv,
        const float* __restrict__ pe, const float* __restrict__ Wpos,
        const float* __restrict__ ce, const float* __restrict__ Wchan,
        float* __restrict__ q, float* __restrict__ kv,
        float* __restrict__ tk, float* __restrict__ ck) {
    __shared__ float As[2][8][128];
    __shared__ float Bs[2][8][128];
    int blk = blockIdx.x;
    if (blk < 128) {
        gemm128_body(hs, Wq, q, Ee, Ee, (blk >> 3) * 128, (blk & 7) * 128, As, Bs);
    } else if (blk < 192) {
        int b = blk - 128;
        gemm128_body(hs, Wkv, kv, 2 * EKVv, Ee, (b >> 2) * 128, (b & 3) * 128, As, Bs);
    } else if (blk < 448) {
        int b = blk - 192;
        skinny_body(pe, Wpos, tk, EKVv, Ee, b >> 1, (b & 1) * 128);
    } else {
        int b = blk - 448;
        skinny_body(ce, Wchan, ck, EKVv, Ee, b >> 1, (b & 1) * 128);
    }
}

// ---------------- standalone GEMM for the output projection ------------------
__global__ __launch_bounds__(256) void sgemm128(
        const float* __restrict__ A, const float* __restrict__ B,
        float* __restrict__ Cmat, int N, int K) {
    __shared__ float As[2][8][128];
    __shared__ float Bs[2][8][128];
    gemm128_body(A, B, Cmat, N, K, blockIdx.y * 128, blockIdx.x * 128, As, Bs);
}

// ---------------- merged time_att + chan_att ---------------------------------
// blocks [0,1024): time (bh = blk%32, t0 = (blk/32)*32)
// blocks [1024,2048): chan
__global__ __launch_bounds__(256) void rel_att_kernel(
        const float* __restrict__ q, const float* __restrict__ bias) {
    __shared__ float qs[32][65];
    __shared__ float ks[128][64];
    int blk = blockIdx.x;
    int tid = threadIdx.x;
    if (blk < 1024) {
        int bh = blk & 31;
        int b = bh / Hh, h = bh % Hh, kvh = h / Gg;
        int t0 = (blk >> 5) * 32;
        for (int i = tid; i < 32 * 64; i += 256) {
            int r = i >> 6, d = i & 63;
            qs[r][d] = q[((size_t)(b * Tt + t0 + r)) * Ee + h * Dd + d]
                     + bias[EKVv + kvh * Dd + d];
        }
        for (int i = tid; i < 128 * 64; i += 256) {
            int p = i >> 6, d = i & 63;
            ks[p][d] = g_tk[p * EKVv + kvh * Dd + d];
        }
        __syncthreads();
        int r = tid & 31;
        int pb = (tid >> 5) * 16;
        float acc[16];
#pragma unroll
        for (int j = 0; j < 16; j++) acc[j] = 0.f;
        for (int d = 0; d < 64; d++) {
            float qv = qs[r][d];
#pragma unroll
            for (int j = 0; j < 16; j++) acc[j] += qv * ks[pb + j][d];
        }
        float* dst = g_time + ((size_t)bh * Tt + t0 + r) * Pp + pb;
#pragma unroll
        for (int j = 0; j < 16; j++) dst[j] = acc[j];
    } else {
        int bc = blk - 1024;
        int bh = bc & 31;
        int b = bh / Hh, h = bh % Hh, kvh = h / Gg;
        int t0 = (bc >> 5) * 32;
        for (int i = tid; i < 32 * 64; i += 256) {
            int r = i >> 6, d = i & 63;
            qs[r][d] = q[((size_t)(b * Tt + t0 + r)) * Ee + h * Dd + d]
                     + bias[2 * EKVv + kvh * Dd + d];
        }
        for (int i = tid; i < 8 * 64; i += 256) {
            int c = i >> 6, d = i & 63;
            ks[c][d] = g_ck[c * EKVv + kvh * Dd + d];
        }
        __syncthreads();
        int r = tid >> 3, c = tid & 7;
        float acc = 0.f;
#pragma unroll
        for (int d = 0; d < 64; d++) acc += qs[r][d] * ks[c][d];
        g_chan[((size_t)bh * Tt + t0 + r) * Cc + c] = acc;
    }
}

// ---------------- attention core: one block per (b, h, pt) -------------------
__global__ __launch_bounds__(256) void attn_kernel(
        const float* __restrict__ q, const float* __restrict__ bias) {
    __shared__ float qg[8][65];      // q + global bias
    __shared__ float lg[8][1025];    // logits -> exp weights
    __shared__ float rinv[8];
    __shared__ float sred[8][8][64]; // [sgroup][c][d] partials
    int blk = blockIdx.x;
    int pt = blk % Pp;
    int h  = (blk / Pp) % Hh;
    int b  = blk / (Pp * Hh);
    int kvh = h / Gg;
    int tid = threadIdx.x;
    int t0 = pt * Cc;

    for (int i = tid; i < 8 * 64; i += 256) {
        int c = i >> 6, d = i & 63;
        qg[c][d] = q[((size_t)(b * Tt + t0 + c)) * Ee + h * Dd + d]
                 + bias[kvh * Dd + d];
    }
    __syncthreads();

    int S = (pt + 1) * Cc;                       // causal extent (patch-level)
    const float* tbase = g_time + (size_t)(b * Hh + h) * Tt * Pp;
    const float* cbase = g_chan + (size_t)(b * Hh + h) * Tt * Cc;

    // base logits: rel-shifted time + rel-shifted chan
    for (int idx = tid; idx < S * 8; idx += 256) {
        int s = idx >> 3, c = idx & 7;
        int t = t0 + c;
        int ps = s >> 3, cs = s & 7;
        unsigned m = (unsigned)(t + 1) * Pp + ps;
        unsigned i2 = m / (Tt + 1);
        float tv = 0.f;
        if (m - i2 * (Tt + 1) != 0) tv = tbase[m - i2 - 1];  // flat-index gather
        int dc = c - cs; dc = dc < 0 ? -dc : dc;
        float cv = cbase[t * Cc + (Cc - 1 - dc)];
        lg[c][s] = tv + cv;
    }
    __syncthreads();

    // global term only inside the wm band (last patch row: everywhere)
    int gLow = (pt == Pp - 1) ? 0 : ((pt > 10 ? pt - 10 : 0) * Cc);
    int nG = (S - gLow) * 8;
    for (int idx = tid; idx < nG; idx += 256) {
        int s = gLow + (idx >> 3);
        int c = idx & 7;
        const float4* gk4 = (const float4*)(g_kv
            + ((size_t)(b * Tt + s)) * (2 * EKVv) + kvh * Dd);
        float acc = 0.f;
#pragma unroll
        for (int d4 = 0; d4 < 16; d4++) {
            float4 gv = gk4[d4];
            acc += qg[c][d4 * 4 + 0] * gv.x + qg[c][d4 * 4 + 1] * gv.y
                 + qg[c][d4 * 4 + 2] * gv.z + qg[c][d4 * 4 + 3] * gv.w;
        }
        lg[c][s] += acc;
    }
    __syncthreads();

    // softmax: warp w owns row w (scale 1/sqrt(D)=0.125 applied here)
    int w = tid >> 5, lane = tid & 31;
    {
        float mx = -1e30f;
        for (int s = lane; s < S; s += 32) mx = fmaxf(mx, lg[w][s] * 0.125f);
#pragma unroll
        for (int o = 16; o > 0; o >>= 1)
            mx = fmaxf(mx, __shfl_xor_sync(0xffffffffu, mx, o));
        float sum = 0.f;
        for (int s = lane; s < S; s += 32) {
            float e = __expf(lg[w][s] * 0.125f - mx);
            lg[w][s] = e;
            sum += e;
        }
#pragma unroll
        for (int o = 16; o > 0; o >>= 1)
            sum += __shfl_xor_sync(0xffffffffu, sum, o);
        if (lane == 0) rinv[w] = 1.f / sum;
    }
    __syncthreads();

    // out[c,d] = sum_s w[c,s]*v[s,d]; thread = (sgroup, d-pair), v loaded ONCE
    // per (s, d-pair) and reused for all 8 c rows (16 FMA per 8B LDG).
    {
        int dp = (tid & 31) * 2;     // d, d+1
        int sg = tid >> 5;           // 0..7
        const float* vbase = g_kv + (size_t)b * Tt * (2 * EKVv) + EKVv
                           + kvh * Dd + dp;
        float accx[8], accy[8];
#pragma unroll
        for (int c = 0; c < 8; c++) { accx[c] = 0.f; accy[c] = 0.f; }
        for (int s = sg; s < S; s += 8) {
            float2 vv = *(const float2*)(vbase + (size_t)s * (2 * EKVv));
#pragma unroll
            for (int c = 0; c < 8; c++) {
                float wgt = lg[c][s];
                accx[c] += wgt * vv.x;
                accy[c] += wgt * vv.y;
            }
        }
#pragma unroll
        for (int c = 0; c < 8; c++) {
            sred[sg][c][dp]     = accx[c];
            sred[sg][c][dp + 1] = accy[c];
        }
    }
    __syncthreads();
    for (int i = tid; i < 512; i += 256) {
        int c = i >> 6, dd = i & 63;
        float o = ((sred[0][c][dd] + sred[1][c][dd])
                 + (sred[2][c][dd] + sred[3][c][dd]))
                + ((sred[4][c][dd] + sred[5][c][dd])
                 + (sred[6][c][dd] + sred[7][c][dd]));
        g_ao[((size_t)(b * Tt + t0 + c)) * Ee + h * Dd + dd] = o * rinv[c];
    }
}

// ---------------- launch ----------------------------------------------------
extern "C" void kernel_launch(void* const* d_in, const int* in_sizes, int n_in,
                              void* d_out, int out_size) {
    const float* hs    = (const float*)d_in[0];
    const float* pe    = (const float*)d_in[1];
    const float* ce    = (const float*)d_in[2];
    const float* Wq    = (const float*)d_in[3];
    const float* Wkv   = (const float*)d_in[4];
    const float* Wpos  = (const float*)d_in[5];
    const float* Wchan = (const float*)d_in[6];
    const float* Wproj = (const float*)d_in[7];
    const float* bias  = (const float*)d_in[8];

    float *q, *kv, *tk, *ck, *ao;
    cudaGetSymbolAddress((void**)&q,  g_q);
    cudaGetSymbolAddress((void**)&kv, g_kv);
    cudaGetSymbolAddress((void**)&tk, g_tk);
    cudaGetSymbolAddress((void**)&ck, g_ck);
    cudaGetSymbolAddress((void**)&ao, g_ao);

    // all projections in one chip-filling launch
    mega_gemm<<<464, 256>>>(hs, Wq, Wkv, pe, Wpos, ce, Wchan, q, kv, tk, ck);

    // relative logits (time + chan merged)
    rel_att_kernel<<<2048, 256>>>(q, bias);

    // attention core
    attn_kernel<<<Bb * Hh * Pp, 256>>>(q, bias);

    // output projection -> d_out
    sgemm128<<<dim3(Ee / 128, (Bb * Tt) / 128), 256>>>(ao, Wproj, (float*)d_out, Ee, Ee);
}